// round 16
// baseline (speedup 1.0000x reference)
#include <cuda_runtime.h>
#include <cuda_bf16.h>
#include <math.h>
#include <stdint.h>

// Problem constants
#define B_   2
#define T_   2048
#define H_   2048
#define NH_  16
#define HD_  128
#define FF_  8192
#define M_   (B_*T_)       // 4096
#define NBATCH (B_*NH_)    // 32
#define EPS_ 1e-5f

// ---------------- scratch (static device globals) ----------------
__device__ __align__(128) __nv_bfloat16 g_h_h [(size_t)M_*H_];
__device__ __align__(128) __nv_bfloat16 g_h_l [(size_t)M_*H_];
__device__ __align__(128) __nv_bfloat16 g_qk_h[(size_t)2*M_*H_];  // q then k, [B,NH,T,HD]
__device__ __align__(128) __nv_bfloat16 g_qk_l[(size_t)2*M_*H_];
__device__ __align__(128) __nv_bfloat16 g_vt_h[(size_t)M_*H_];    // [B,NH,HD,T]
__device__ __align__(128) __nv_bfloat16 g_vt_l[(size_t)M_*H_];
__device__ __align__(128) __nv_bfloat16 g_at_h[(size_t)M_*H_];    // attn [B,T,H]
__device__ __align__(128) __nv_bfloat16 g_at_l[(size_t)M_*H_];
__device__ __align__(128) __nv_bfloat16 g_f_h [(size_t)M_*FF_];
__device__ __align__(128) __nv_bfloat16 g_f_l [(size_t)M_*FF_];
__device__ __align__(128) float g_x2[(size_t)M_*H_];
__device__ __align__(128) float g_pp[(size_t)2*M_*H_];            // split-K partials
// transposed split weights [N,K]
__device__ __align__(128) __nv_bfloat16 g_wqk_h[(size_t)2*H_*H_]; // wq then wk
__device__ __align__(128) __nv_bfloat16 g_wqk_l[(size_t)2*H_*H_];
__device__ __align__(128) __nv_bfloat16 g_wv_h[(size_t)H_*H_];
__device__ __align__(128) __nv_bfloat16 g_wv_l[(size_t)H_*H_];
__device__ __align__(128) __nv_bfloat16 g_wo_h[(size_t)H_*H_];
__device__ __align__(128) __nv_bfloat16 g_wo_l[(size_t)H_*H_];
__device__ __align__(128) __nv_bfloat16 g_w1_h[(size_t)FF_*H_];
__device__ __align__(128) __nv_bfloat16 g_w1_l[(size_t)FF_*H_];
__device__ __align__(128) __nv_bfloat16 g_w2_h[(size_t)H_*FF_];
__device__ __align__(128) __nv_bfloat16 g_w2_l[(size_t)H_*FF_];

// ---------------- PTX helpers (all arch-portable: sm_80+) ----------------
__device__ __forceinline__ uint32_t smem_u32(const void* p) {
    uint32_t a;
    asm("{ .reg .u64 t; cvta.to.shared.u64 t, %1; cvt.u32.u64 %0, t; }" : "=r"(a) : "l"(p));
    return a;
}
#define SW128(o) ((o) ^ (((o) >> 3) & 0x70))
#define SW64(o)  ((o) ^ (((o) >> 3) & 0x30))

__device__ __forceinline__ void cpa16(uint32_t s, const void* g) {
    asm volatile("cp.async.cg.shared.global [%0], [%1], 16;" :: "r"(s), "l"(g) : "memory");
}
__device__ __forceinline__ void cpa_commit() {
    asm volatile("cp.async.commit_group;" ::: "memory");
}
template<int N> __device__ __forceinline__ void cpa_wait() {
    asm volatile("cp.async.wait_group %0;" :: "n"(N) : "memory");
}

#define LDSM4(r, addr) \
    asm volatile("ldmatrix.sync.aligned.m8n8.x4.shared.b16 {%0,%1,%2,%3}, [%4];" \
        : "=r"((r)[0]), "=r"((r)[1]), "=r"((r)[2]), "=r"((r)[3]) : "r"(addr))

#define MMA_BF16(d, a, b) \
    asm volatile("mma.sync.aligned.m16n8k16.row.col.f32.bf16.bf16.f32 " \
        "{%0,%1,%2,%3},{%4,%5,%6,%7},{%8,%9},{%0,%1,%2,%3};" \
        : "+f"((d)[0]), "+f"((d)[1]), "+f"((d)[2]), "+f"((d)[3]) \
        : "r"((a)[0]), "r"((a)[1]), "r"((a)[2]), "r"((a)[3]), "r"((b)[0]), "r"((b)[1]))

// ---------------- misc helpers ----------------
__device__ __forceinline__ float gelu_tanh_f(float x) {
    float x3 = x * x * x;
    float t  = tanhf(0.7978845608028654f * (x + 0.044715f * x3));
    return 0.5f * x * (1.0f + t);
}
__device__ __forceinline__ void st_split2(__nv_bfloat16* ph, __nv_bfloat16* pl, float a, float b) {
    __nv_bfloat16 ha = __float2bfloat16(a), hb = __float2bfloat16(b);
    __nv_bfloat162 hp = __halves2bfloat162(ha, hb);
    __nv_bfloat162 lp = __halves2bfloat162(__float2bfloat16(a - __bfloat162float(ha)),
                                           __float2bfloat16(b - __bfloat162float(hb)));
    *(uint32_t*)ph = *(uint32_t*)&hp;
    *(uint32_t*)pl = *(uint32_t*)&lp;
}
__device__ __forceinline__ uint32_t pack_split_hi(float a, float b, uint32_t* lo) {
    __nv_bfloat16 ha = __float2bfloat16(a), hb = __float2bfloat16(b);
    __nv_bfloat162 hp = __halves2bfloat162(ha, hb);
    __nv_bfloat162 lp = __halves2bfloat162(__float2bfloat16(a - __bfloat162float(ha)),
                                           __float2bfloat16(b - __bfloat162float(hb)));
    *lo = *(uint32_t*)&lp;
    return *(uint32_t*)&hp;
}

// ---------------- weight transpose + split (vectorized) ----------------
__global__ __launch_bounds__(256)
void wsplitT(const float* __restrict__ W, __nv_bfloat16* __restrict__ Th,
             __nv_bfloat16* __restrict__ Tl, int K, int N)
{
    __shared__ float t[64][33];
    int n0 = blockIdx.x * 32, k0 = blockIdx.y * 64;
    int tx = threadIdx.x, ty = threadIdx.y;
#pragma unroll
    for (int r = ty; r < 64; r += 8)
        t[r][tx] = W[(size_t)(k0 + r) * N + n0 + tx];
    __syncthreads();
#pragma unroll
    for (int n = ty; n < 32; n += 8) {
        float a = t[2 * tx][n], b = t[2 * tx + 1][n];
        uint32_t lo;
        uint32_t hi = pack_split_hi(a, b, &lo);
        size_t idx = (size_t)(n0 + n) * K + k0 + 2 * tx;
        *(uint32_t*)(Th + idx) = hi;
        *(uint32_t*)(Tl + idx) = lo;
    }
}

__global__ __launch_bounds__(256)
void wsplitT4(const float* __restrict__ w0, const float* __restrict__ w1,
              const float* __restrict__ w2, const float* __restrict__ w3,
              __nv_bfloat16* __restrict__ t0h, __nv_bfloat16* __restrict__ t0l,
              __nv_bfloat16* __restrict__ t1h, __nv_bfloat16* __restrict__ t1l,
              __nv_bfloat16* __restrict__ t2h, __nv_bfloat16* __restrict__ t2l,
              __nv_bfloat16* __restrict__ t3h, __nv_bfloat16* __restrict__ t3l)
{
    __shared__ float t[64][33];
    int z = blockIdx.z;
    const float* W = (z == 0) ? w0 : (z == 1) ? w1 : (z == 2) ? w2 : w3;
    __nv_bfloat16* Th = (z == 0) ? t0h : (z == 1) ? t1h : (z == 2) ? t2h : t3h;
    __nv_bfloat16* Tl = (z == 0) ? t0l : (z == 1) ? t1l : (z == 2) ? t2l : t3l;
    int n0 = blockIdx.x * 32, k0 = blockIdx.y * 64;
    int tx = threadIdx.x, ty = threadIdx.y;
#pragma unroll
    for (int r = ty; r < 64; r += 8)
        t[r][tx] = W[(size_t)(k0 + r) * H_ + n0 + tx];
    __syncthreads();
#pragma unroll
    for (int n = ty; n < 32; n += 8) {
        float a = t[2 * tx][n], b = t[2 * tx + 1][n];
        uint32_t lo;
        uint32_t hi = pack_split_hi(a, b, &lo);
        size_t idx = (size_t)(n0 + n) * H_ + k0 + 2 * tx;
        *(uint32_t*)(Th + idx) = hi;
        *(uint32_t*)(Tl + idx) = lo;
    }
}

// ---------------- LayerNorm -> bf16 hi/lo ----------------
__global__ __launch_bounds__(256)
void ln_kernel(const float* __restrict__ x, const float* __restrict__ sc,
               const float* __restrict__ sh,
               __nv_bfloat16* __restrict__ oh, __nv_bfloat16* __restrict__ ol)
{
    __shared__ float red[8];
    int row = blockIdx.x;
    int tid = threadIdx.x;
    const float* xr = x + (size_t)row * H_;

    float v[8];
    float s = 0.f;
#pragma unroll
    for (int i = 0; i < 8; i++) { v[i] = xr[i * 256 + tid]; s += v[i]; }
#pragma unroll
    for (int o = 16; o > 0; o >>= 1) s += __shfl_xor_sync(0xffffffffu, s, o);
    if ((tid & 31) == 0) red[tid >> 5] = s;
    __syncthreads();
    float tot = 0.f;
#pragma unroll
    for (int i = 0; i < 8; i++) tot += red[i];
    __syncthreads();
    float mean = tot * (1.0f / H_);

    float s2 = 0.f;
#pragma unroll
    for (int i = 0; i < 8; i++) { float d = v[i] - mean; s2 += d * d; }
#pragma unroll
    for (int o = 16; o > 0; o >>= 1) s2 += __shfl_xor_sync(0xffffffffu, s2, o);
    if ((tid & 31) == 0) red[tid >> 5] = s2;
    __syncthreads();
    float tot2 = 0.f;
#pragma unroll
    for (int i = 0; i < 8; i++) tot2 += red[i];

    float inv = rsqrtf(tot2 * (1.0f / H_) + EPS_);
    size_t rb = (size_t)row * H_;
#pragma unroll
    for (int i = 0; i < 8; i++) {
        int col = i * 256 + tid;
        float val = sc[col] * ((v[i] - mean) * inv) + sh[col];
        __nv_bfloat16 h = __float2bfloat16(val);
        oh[rb + col] = h;
        ol[rb + col] = __float2bfloat16(val - __bfloat162float(h));
    }
}

// ---------------- fused split-K combine (Wo) + residual + LN2 ----------------
__global__ __launch_bounds__(256)
void combine_ln(const float* __restrict__ p0, const float* __restrict__ p1,
                const float* __restrict__ res,
                const float* __restrict__ sc, const float* __restrict__ sh,
                float* __restrict__ x2, __nv_bfloat16* __restrict__ oh,
                __nv_bfloat16* __restrict__ ol)
{
    __shared__ float red[8];
    int row = blockIdx.x;
    int tid = threadIdx.x;
    size_t rb = (size_t)row * H_;

    float v[8];
    float s = 0.f;
#pragma unroll
    for (int i = 0; i < 8; i++) {
        int col = i * 256 + tid;
        float val = p0[rb + col] + p1[rb + col] + res[rb + col];
        x2[rb + col] = val;
        v[i] = val;
        s += val;
    }
#pragma unroll
    for (int o = 16; o > 0; o >>= 1) s += __shfl_xor_sync(0xffffffffu, s, o);
    if ((tid & 31) == 0) red[tid >> 5] = s;
    __syncthreads();
    float tot = 0.f;
#pragma unroll
    for (int i = 0; i < 8; i++) tot += red[i];
    __syncthreads();
    float mean = tot * (1.0f / H_);

    float s2 = 0.f;
#pragma unroll
    for (int i = 0; i < 8; i++) { float d = v[i] - mean; s2 += d * d; }
#pragma unroll
    for (int o = 16; o > 0; o >>= 1) s2 += __shfl_xor_sync(0xffffffffu, s2, o);
    if ((tid & 31) == 0) red[tid >> 5] = s2;
    __syncthreads();
    float tot2 = 0.f;
#pragma unroll
    for (int i = 0; i < 8; i++) tot2 += red[i];

    float inv = rsqrtf(tot2 * (1.0f / H_) + EPS_);
#pragma unroll
    for (int i = 0; i < 8; i++) {
        int col = i * 256 + tid;
        float val = sc[col] * ((v[i] - mean) * inv) + sh[col];
        __nv_bfloat16 h = __float2bfloat16(val);
        oh[rb + col] = h;
        ol[rb + col] = __float2bfloat16(val - __bfloat162float(h));
    }
}

// ---------------- split-K combine: out = p0 + p1 + res + bias ----------------
__global__ __launch_bounds__(256)
void combine2(const float* __restrict__ p0, const float* __restrict__ p1,
              const float* __restrict__ res, const float* __restrict__ bias,
              float* __restrict__ out)
{
    size_t i4 = (size_t)blockIdx.x * 256 + threadIdx.x;
    size_t base = i4 * 4;
    float4 a = *(const float4*)(p0 + base);
    float4 b = *(const float4*)(p1 + base);
    float4 r = *(const float4*)(res + base);
    float4 o;
    o.x = a.x + b.x + r.x;
    o.y = a.y + b.y + r.y;
    o.z = a.z + b.z + r.z;
    o.w = a.w + b.w + r.w;
    if (bias) {
        int col = (int)(base & (H_ - 1));
        o.x += bias[col]; o.y += bias[col + 1]; o.z += bias[col + 2]; o.w += bias[col + 3];
    }
    *(float4*)(out + base) = o;
}

// ---------------- merged QKV GEMM (z=0:q *alpha, 1:k, 2:v transposed) ----------------
__global__ __launch_bounds__(256)
void qkv_gemm(const __nv_bfloat16* __restrict__ Ah, const __nv_bfloat16* __restrict__ Al,
              const __nv_bfloat16* __restrict__ Bqkh, const __nv_bfloat16* __restrict__ Bqkl,
              const __nv_bfloat16* __restrict__ Bvh, const __nv_bfloat16* __restrict__ Bvl,
              __nv_bfloat16* __restrict__ Cqh, __nv_bfloat16* __restrict__ Cql,
              __nv_bfloat16* __restrict__ Cvh, __nv_bfloat16* __restrict__ Cvl,
              float alpha)
{
    int bn = blockIdx.x, bm = blockIdx.y, z = blockIdx.z;
    const int NCH = H_ >> 6;

    extern __shared__ char smem[];
    uint32_t sb = smem_u32(smem);
    const uint32_t STG = 65536;

    int tid = threadIdx.x, wid = tid >> 5, lane = tid & 31;
    int wm = wid >> 1, wn = wid & 1;

    const __nv_bfloat16* Agh = Ah + (size_t)(bm * 128) * H_;
    const __nv_bfloat16* Agl = Al + (size_t)(bm * 128) * H_;
    const __nv_bfloat16* Bgh = ((z == 2) ? Bvh : Bqkh + (size_t)z * H_ * H_) + (size_t)(bn * 128) * H_;
    const __nv_bfloat16* Bgl = ((z == 2) ? Bvl : Bqkl + (size_t)z * H_ * H_) + (size_t)(bn * 128) * H_;

    auto ldst = [&](int i, int st) {
        uint32_t base = sb + st * STG;
        int k0 = i << 6;
#pragma unroll
        for (int p = tid; p < 1024; p += 256) {
            int r = p >> 3, c = p & 7;
            uint32_t so = SW128(r * 128 + c * 16);
            size_t go = (size_t)r * H_ + k0 + c * 8;
            cpa16(base + so,         Agh + go);
            cpa16(base + 16384 + so, Agl + go);
            cpa16(base + 32768 + so, Bgh + go);
            cpa16(base + 49152 + so, Bgl + go);
        }
        cpa_commit();
    };

    float acc[2][8][4];
#pragma unroll
    for (int mi = 0; mi < 2; mi++)
#pragma unroll
        for (int ni = 0; ni < 8; ni++)
#pragma unroll
            for (int r = 0; r < 4; r++) acc[mi][ni][r] = 0.f;

    ldst(0, 0);

    for (int i = 0; i < NCH; i++) {
        int st = i & 1;
        cpa_wait<0>();
        __syncthreads();
        if (i + 1 < NCH) ldst(i + 1, (i + 1) & 1);

        uint32_t base = sb + st * STG;
#pragma unroll
        for (int ks = 0; ks < 4; ks++) {
            uint32_t ah[2][4], al[2][4];
#pragma unroll
            for (int mi = 0; mi < 2; mi++) {
                int row = wm * 32 + mi * 16 + (lane & 15);
                uint32_t kb = ks * 32 + ((lane >> 4) << 4);
                uint32_t ad = base + SW128((uint32_t)(row * 128) + kb);
                LDSM4(ah[mi], ad);
                LDSM4(al[mi], ad + 16384);
            }
            uint32_t bh[4][4], bl[4][4];
#pragma unroll
            for (int g = 0; g < 4; g++) {
                int nrow = wn * 64 + g * 16 + (lane & 7) + ((lane >> 4) << 3);
                uint32_t kb = ks * 32 + (((lane >> 3) & 1) << 4);
                uint32_t ad = base + 32768 + SW128((uint32_t)(nrow * 128) + kb);
                LDSM4(bh[g], ad);
                LDSM4(bl[g], ad + 16384);
            }
#pragma unroll
            for (int mi = 0; mi < 2; mi++)
#pragma unroll
                for (int ni = 0; ni < 8; ni++) {
                    uint32_t* pbh = &bh[ni >> 1][(ni & 1) * 2];
                    uint32_t* pbl = &bl[ni >> 1][(ni & 1) * 2];
                    MMA_BF16(acc[mi][ni], ah[mi], pbh);
                    MMA_BF16(acc[mi][ni], ah[mi], pbl);
                    MMA_BF16(acc[mi][ni], al[mi], pbh);
                }
        }
    }

    if (z == 2) {
        __syncthreads();
        float* sf = (float*)smem;                       // [128][132]
#pragma unroll
        for (int mi = 0; mi < 2; mi++)
#pragma unroll
            for (int ni = 0; ni < 8; ni++)
#pragma unroll
                for (int half = 0; half < 2; half++) {
                    int r = wm * 32 + mi * 16 + (lane >> 2) + half * 8;
                    int c = wn * 64 + ni * 8 + (lane & 3) * 2;
                    sf[r * 132 + c]     = acc[mi][ni][half * 2 + 0];
                    sf[r * 132 + c + 1] = acc[mi][ni][half * 2 + 1];
                }
        __syncthreads();

        int d  = tid >> 1;
        int t0 = (tid & 1) * 64;
        int b  = (bm * 128) >> 11;
        int hh = bn;
        int tloc = (bm & (T_ / 128 - 1)) * 128;
        size_t obase = ((size_t)(b * NH_ + hh) * HD_ + d) * T_ + (size_t)tloc + t0;

        uint32_t hbuf[32], lbuf[32];
#pragma unroll
        for (int q = 0; q < 32; q++) {
            float a  = sf[(t0 + 2 * q)     * 132 + d];
            float c2 = sf[(t0 + 2 * q + 1) * 132 + d];
            hbuf[q] = pack_split_hi(a, c2, &lbuf[q]);
        }
        uint4* ph4 = (uint4*)(Cvh + obase);
        uint4* pl4 = (uint4*)(Cvl + obase);
#pragma unroll
        for (int g = 0; g < 8; g++) {
            ph4[g] = make_uint4(hbuf[4*g], hbuf[4*g+1], hbuf[4*g+2], hbuf[4*g+3]);
            pl4[g] = make_uint4(lbuf[4*g], lbuf[4*g+1], lbuf[4*g+2], lbuf[4*g+3]);
        }
        return;
    }

    float a = (z == 0) ? alpha : 1.0f;
#pragma unroll
    for (int mi = 0; mi < 2; mi++) {
#pragma unroll
        for (int ni = 0; ni < 8; ni++) {
            int row0 = bm * 128 + wm * 32 + mi * 16 + (lane >> 2);
            int col  = bn * 128 + wn * 64 + ni * 8 + (lane & 3) * 2;
#pragma unroll
            for (int half = 0; half < 2; half++) {
                int gm = row0 + half * 8;
                float v0 = acc[mi][ni][half * 2 + 0] * a;
                float v1 = acc[mi][ni][half * 2 + 1] * a;
                int b = gm >> 11, t = gm & (T_ - 1);
                int hh = col >> 7, d = col & 127;
                size_t idx = (size_t)z * M_ * H_ +
                             (((size_t)(b * NH_ + hh) * T_ + t) << 7) + d;
                st_split2(Cqh + idx, Cql + idx, v0, v1);
            }
        }
    }
}

// ---------------- mma.sync split-bf16 GEMM (FFN + Wo), BK=32, 2 CTAs/SM ----------------
// stage (32KB): Ah@0, Al@8K, Bh@16K, Bl@24K (SW64, 64B rows); 2 stages = 64KB
// EPI: 6 bias+gelu -> hi/lo; 8 split-K f32 partial (z = k-half)
template<int EPI>
__global__ __launch_bounds__(256, 2)
void mgemm(const __nv_bfloat16* __restrict__ Ah, const __nv_bfloat16* __restrict__ Al,
           const __nv_bfloat16* __restrict__ Bh, const __nv_bfloat16* __restrict__ Bl,
           float* __restrict__ Cf, __nv_bfloat16* __restrict__ Ch, __nv_bfloat16* __restrict__ Cl,
           const float* __restrict__ bias, const float* __restrict__ res,
           int K, int lda, int ldb, float alpha, size_t sA, size_t sB)
{
    int bn = blockIdx.x, bm = blockIdx.y, z = blockIdx.z;
    const int NCH = K >> 5;

    extern __shared__ char smem[];
    uint32_t sb = smem_u32(smem);
    const uint32_t STG = 32768;

    int tid = threadIdx.x, wid = tid >> 5, lane = tid & 31;
    int wm = wid >> 1, wn = wid & 1;

    const __nv_bfloat16* Agh = Ah + (size_t)z * sA + (size_t)(bm * 128) * lda;
    const __nv_bfloat16* Agl = Al + (size_t)z * sA + (size_t)(bm * 128) * lda;
    const __nv_bfloat16* Bgh = Bh + (size_t)z * sB + (size_t)(bn * 128) * ldb;
    const __nv_bfloat16* Bgl = Bl + (size_t)z * sB + (size_t)(bn * 128) * ldb;

    auto ldst = [&](int i, int st) {
        uint32_t base = sb + st * STG;
        int k0 = i << 5;
#pragma unroll
        for (int p = tid; p < 512; p += 256) {
            int r = p >> 2, c = p & 3;
            uint32_t so = SW64(r * 64 + c * 16);
            size_t goa = (size_t)r * lda + k0 + c * 8;
            size_t gob = (size_t)r * ldb + k0 + c * 8;
            cpa16(base + so,         Agh + goa);
            cpa16(base + 8192 + so,  Agl + goa);
            cpa16(base + 16384 + so, Bgh + gob);
            cpa16(base + 24576 + so, Bgl + gob);
        }
        cpa_commit();
    };

    float acc[2][8][4];
#pragma unroll
    for (int mi = 0; mi < 2; mi++)
#pragma unroll
        for (int ni = 0; ni < 8; ni++)
#pragma unroll
            for (int r = 0; r < 4; r++) acc[mi][ni][r] = 0.f;

    ldst(0, 0);

    for (int i = 0; i < NCH; i++) {
        int st = i & 1;
        cpa_wait<0>();
        __syncthreads();
        if (i + 1 < NCH) ldst(i + 1, (i + 1) & 1);

        uint32_t base = sb + st * STG;
#pragma unroll
        for (int ks = 0; ks < 2; ks++) {
            uint32_t ah[2][4], al[2][4];
#pragma unroll
            for (int mi = 0; mi < 2; mi++) {
                int row = wm * 32 + mi * 16 + (lane & 15);
                uint32_t kb = ks * 32 + ((lane >> 4) << 4);
                uint32_t ad = base + SW64((uint32_t)(row * 64) + kb);
                LDSM4(ah[mi], ad);
                LDSM4(al[mi], ad + 8192);
            }
#pragma unroll
            for (int g = 0; g < 4; g++) {
                int nrow = wn * 64 + g * 16 + (lane & 7) + ((lane >> 4) << 3);
                uint32_t kb = ks * 32 + (((lane >> 3) & 1) << 4);
                uint32_t ad = base + 16384 + SW64((uint32_t)(nrow * 64) + kb);
                uint32_t bh4[4], bl4[4];
                LDSM4(bh4, ad);
                LDSM4(bl4, ad + 8192);
#pragma unroll
                for (int sub = 0; sub < 2; sub++) {
                    int ni = g * 2 + sub;
#pragma unroll
                    for (int mi = 0; mi < 2; mi++) {
                        MMA_BF16(acc[mi][ni], ah[mi], &bh4[sub * 2]);
                        MMA_BF16(acc[mi][ni], ah[mi], &bl4[sub * 2]);
                        MMA_BF16(acc[mi][ni], al[mi], &bh4[sub * 2]);
                    }
                }
            }
        }
    }

#pragma unroll
    for (int mi = 0; mi < 2; mi++) {
#pragma unroll
        for (int ni = 0; ni < 8; ni++) {
            int row0 = bm * 128 + wm * 32 + mi * 16 + (lane >> 2);
            int col  = bn * 128 + wn * 64 + ni * 8 + (lane & 3) * 2;
#pragma unroll
            for (int half = 0; half < 2; half++) {
                int gm = row0 + half * 8;
                float v0 = acc[mi][ni][half * 2 + 0];
                float v1 = acc[mi][ni][half * 2 + 1];

                if (EPI == 6) {
                    v0 = gelu_tanh_f(v0 + bias[col]);
                    v1 = gelu_tanh_f(v1 + bias[col + 1]);
                    size_t idx = (size_t)gm * FF_ + col;
                    st_split2(Ch + idx, Cl + idx, v0, v1);
                } else if (EPI == 8) {
                    float2* p = (float2*)(Cf + (size_t)z * M_ * H_ + (size_t)gm * H_ + col);
                    *p = make_float2(v0, v1);
                }
            }
        }
    }
}

// ---------------- fused flash attention ----------------
#define FA_SMEM 131072
__global__ __launch_bounds__(256)
void fa_kernel(const __nv_bfloat16* __restrict__ Qh, const __nv_bfloat16* __restrict__ Ql,
               const __nv_bfloat16* __restrict__ Kh, const __nv_bfloat16* __restrict__ Kl,
               const __nv_bfloat16* __restrict__ Vth, const __nv_bfloat16* __restrict__ Vtl,
               __nv_bfloat16* __restrict__ Ch, __nv_bfloat16* __restrict__ Cl)
{
    int bm = (int)gridDim.y - 1 - (int)blockIdx.y;   // longest first
    int z  = blockIdx.z;
    const int NCH = (bm + 1) * 2;                    // 64-token chunks

    extern __shared__ char smem[];
    uint32_t sb = smem_u32(smem);
    const uint32_t STG = 65536;

    int tid = threadIdx.x, w = tid >> 5, lane = tid & 31;

    const __nv_bfloat16* Qgh = Qh + (size_t)z * T_ * HD_ + (size_t)(bm * 128) * HD_;
    const __nv_bfloat16* Qgl = Ql + (size_t)z * T_ * HD_ + (size_t)(bm * 128) * HD_;
    const __nv_bfloat16* Kgh = Kh + (size_t)z * T_ * HD_;
    const __nv_bfloat16* Kgl = Kl + (size_t)z * T_ * HD_;
    const __nv_bfloat16* Vgh = Vth + (size_t)z * HD_ * T_;
    const __nv_bfloat16* Vgl = Vtl + (size_t)z * HD_ * T_;

#pragma unroll
    for (int p = tid; p < 2048; p += 256) {
        int r = p >> 4, c = p & 15;
        uint32_t so = (uint32_t)(c >> 3) * 16384 + SW128((uint32_t)(r * 128) + (c & 7) * 16);
        cpa16(sb + so,         Qgh + (size_t)r * HD_ + c * 8);
        cpa16(sb + 32768 + so, Qgl + (size_t)r * HD_ + c * 8);
    }
    cpa_commit();
    cpa_wait<0>();
    __syncthreads();

    uint32_t qh[8][4], ql[8][4];
#pragma unroll
    for (int ks = 0; ks < 8; ks++) {
        int row = w * 16 + (lane & 15);
        uint32_t kb = (uint32_t)(ks & 3) * 32 + ((lane >> 4) << 4);
        uint32_t ad = sb + (uint32_t)(ks >> 2) * 16384 + SW128((uint32_t)(row * 128) + kb);
        LDSM4(qh[ks], ad);
        LDSM4(ql[ks], ad + 32768);
    }
    __syncthreads();

    auto ldst = [&](int kt, int st) {
        uint32_t base = sb + st * STG;
#pragma unroll
        for (int p = tid; p < 1024; p += 256) {       // K: 64 rows x 256B
            int r = p >> 4, c = p & 15;
            uint32_t so = (uint32_t)(c >> 3) * 8192 + SW128((uint32_t)(r * 128) + (c & 7) * 16);
            size_t go = (size_t)(kt * 64 + r) * HD_ + c * 8;
            cpa16(base + so,         Kgh + go);
            cpa16(base + 16384 + so, Kgl + go);
        }
#pragma unroll
        for (int p = tid; p < 1024; p += 256) {       // V: 128 rows x 128B
            int r = p >> 3, c = p & 7;
            uint32_t so = SW128((uint32_t)(r * 128) + c * 16);
            size_t go = (size_t)r * T_ + kt * 64 + c * 8;
            cpa16(base + 32768 + so, Vgh + go);
            cpa16(base + 49152 + so, Vgl + go);
        }
        cpa_commit();
    };

    float m[2] = {-1e30f, -1e30f}, l[2] = {0.f, 0.f};
    float acc[16][4];
#pragma unroll
    for (int ni = 0; ni < 16; ni++)
#pragma unroll
        for (int r = 0; r < 4; r++) acc[ni][r] = 0.f;

    ldst(0, 0);

    int gmin = bm * 128 + w * 16;

    for (int i = 0; i < NCH; i++) {
        int st = i & 1;
        cpa_wait<0>();
        __syncthreads();
        if (i + 1 < NCH) ldst(i + 1, (i + 1) & 1);

        uint32_t base = sb + st * STG;

        float s[8][4];
#pragma unroll
        for (int ni = 0; ni < 8; ni++)
#pragma unroll
            for (int r = 0; r < 4; r++) s[ni][r] = 0.f;

#pragma unroll
        for (int ks = 0; ks < 8; ks++) {
            uint32_t kb = (uint32_t)(ks & 3) * 32 + (((lane >> 3) & 1) << 4);
            uint32_t kbase = base + (uint32_t)(ks >> 2) * 8192;
#pragma unroll
            for (int g = 0; g < 4; g++) {
                int nrow = g * 16 + (lane & 7) + ((lane >> 4) << 3);
                uint32_t ad = kbase + SW128((uint32_t)(nrow * 128) + kb);
                uint32_t kh4[4], kl4[4];
                LDSM4(kh4, ad);
                LDSM4(kl4, ad + 16384);
#pragma unroll
                for (int sub = 0; sub < 2; sub++) {
                    int ni = g * 2 + sub;
                    MMA_BF16(s[ni], qh[ks], &kh4[sub * 2]);
                    MMA_BF16(s[ni], qh[ks], &kl4[sub * 2]);
                    MMA_BF16(s[ni], ql[ks], &kh4[sub * 2]);
                }
            }
        }

        int jb = i * 64;
        if (jb + 63 > gmin) {
#pragma unroll
            for (int ni = 0; ni < 8; ni++)
#pragma unroll
                for (int half = 0; half < 2; half++) {
                    int gi2 = gmin + (lane >> 2) + half * 8;
                    int j0  = jb + ni * 8 + (lane & 3) * 2;
                    if (j0 > gi2)     s[ni][half * 2]     = -1e30f;
                    if (j0 + 1 > gi2) s[ni][half * 2 + 1] = -1e30f;
                }
        }

        uint32_t pah[4][4], pal[4][4];
        float rfac[2];
#pragma unroll
        for (int half = 0; half < 2; half++) {
            float mx = -1e30f;
#pragma unroll
            for (int ni = 0; ni < 8; ni++) {
                mx = fmaxf(mx, s[ni][half * 2]);
                mx = fmaxf(mx, s[ni][half * 2 + 1]);
            }
            mx = fmaxf(mx, __shfl_xor_sync(0xffffffffu, mx, 1));
            mx = fmaxf(mx, __shfl_xor_sync(0xffffffffu, mx, 2));
            float mnew = fmaxf(m[half], mx);
            rfac[half] = __expf(m[half] - mnew);
            m[half] = mnew;

            float psum = 0.f;
#pragma unroll
            for (int ni = 0; ni < 8; ni++) {
                float p0 = __expf(s[ni][half * 2]     - mnew);
                float p1 = __expf(s[ni][half * 2 + 1] - mnew);
                psum += p0 + p1;
                uint32_t lo;
                uint32_t hi = pack_split_hi(p0, p1, &lo);
                pah[ni >> 1][(ni & 1) * 2 + half] = hi;
                pal[ni >> 1][(ni & 1) * 2 + half] = lo;
            }
            psum += __shfl_xor_sync(0xffffffffu, psum, 1);
            psum += __shfl_xor_sync(0xffffffffu, psum, 2);
            l[half] = l[half] * rfac[half] + psum;
        }

#pragma unroll
        for (int ni = 0; ni < 16; ni++) {
            acc[ni][0] *= rfac[0]; acc[ni][1] *= rfac[0];
            acc[ni][2] *= rfac[1]; acc[ni][3] *= rfac[1];
        }

#pragma unroll
        for (int ks2 = 0; ks2 < 4; ks2++) {
            uint32_t kb = (uint32_t)ks2 * 32 + (((lane >> 3) & 1) << 4);
#pragma unroll
            for (int g = 0; g < 8; g++) {
                int nrow = g * 16 + (lane & 7) + ((lane >> 4) << 3);
                uint32_t ad = base + 32768 + SW128((uint32_t)(nrow * 128) + kb);
                uint32_t vh4[4], vl4[4];
                LDSM4(vh4, ad);
                LDSM4(vl4, ad + 16384);
#pragma unroll
                for (int sub = 0; sub < 2; sub++) {
                    int ni = g * 2 + sub;
                    MMA_BF16(acc[ni], pah[ks2], &vh4[sub * 2]);
                    MMA_BF16(acc[ni], pah[ks2], &vl4[sub * 2]);
                    MMA_BF16(acc[ni], pal[ks2], &vh4[sub * 2]);
                }
            }
        }
    }

    int b  = z >> 4, hh = z & 15;
#pragma unroll
    for (int half = 0; half < 2; half++) {
        float linv = 1.0f / l[half];
        int gm = gmin + (lane >> 2) + half * 8;
#pragma unroll
        for (int ni = 0; ni < 16; ni++) {
            int col = ni * 8 + (lane & 3) * 2;
            float v0 = acc[ni][half * 2]     * linv;
            float v1 = acc[ni][half * 2 + 1] * linv;
            size_t idx = ((size_t)(b * T_ + gm)) * H_ + hh * HD_ + col;
            st_split2(Ch + idx, Cl + idx, v0, v1);
        }
    }
}

// ---------------- launch ----------------
extern "C" void kernel_launch(void* const* d_in, const int* in_sizes, int n_in,
                              void* d_out, int out_size)
{
    (void)in_sizes; (void)n_in; (void)out_size;
    const float* x    = (const float*)d_in[0];
    const float* wq   = (const float*)d_in[1];
    const float* wk   = (const float*)d_in[2];
    const float* wv   = (const float*)d_in[3];
    const float* wo   = (const float*)d_in[4];
    const float* ln1s = (const float*)d_in[5];
    const float* ln1b = (const float*)d_in[6];
    const float* ln2s = (const float*)d_in[7];
    const float* ln2b = (const float*)d_in[8];
    const float* w1   = (const float*)d_in[9];
    const float* b1   = (const float*)d_in[10];
    const float* w2   = (const float*)d_in[11];
    const float* b2   = (const float*)d_in[12];
    float* out = (float*)d_out;

    __nv_bfloat16 *h_h,*h_l,*qk_h,*qk_l,*vt_h,*vt_l,*at_h,*at_l,*f_h,*f_l;
    __nv_bfloat16 *wqk_h,*wqk_l,*wvt_h,*wvt_l,*wot_h,*wot_l,*w1t_h,*w1t_l,*w2t_h,*w2t_l;
    float *x2, *pp;
    cudaGetSymbolAddress((void**)&h_h, g_h_h);   cudaGetSymbolAddress((void**)&h_l, g_h_l);
    cudaGetSymbolAddress((void**)&qk_h, g_qk_h); cudaGetSymbolAddress((void**)&qk_l, g_qk_l);
    cudaGetSymbolAddress((void**)&vt_h, g_vt_h); cudaGetSymbolAddress((void**)&vt_l, g_vt_l);
    cudaGetSymbolAddress((void**)&at_h, g_at_h); cudaGetSymbolAddress((void**)&at_l, g_at_l);
    cudaGetSymbolAddress((void**)&f_h, g_f_h);   cudaGetSymbolAddress((void**)&f_l, g_f_l);
    cudaGetSymbolAddress((void**)&wqk_h, g_wqk_h); cudaGetSymbolAddress((void**)&wqk_l, g_wqk_l);
    cudaGetSymbolAddress((void**)&wvt_h, g_wv_h); cudaGetSymbolAddress((void**)&wvt_l, g_wv_l);
    cudaGetSymbolAddress((void**)&wot_h, g_wo_h); cudaGetSymbolAddress((void**)&wot_l, g_wo_l);
    cudaGetSymbolAddress((void**)&w1t_h, g_w1_h); cudaGetSymbolAddress((void**)&w1t_l, g_w1_l);
    cudaGetSymbolAddress((void**)&w2t_h, g_w2_h); cudaGetSymbolAddress((void**)&w2t_l, g_w2_l);
    cudaGetSymbolAddress((void**)&x2, g_x2);
    cudaGetSymbolAddress((void**)&pp, g_pp);

    const int SMEM  = 131072;  // qkv: 2 stages x 64KB
    const int SMEM2 = 65536;   // mgemm: 2 stages x 32KB (2 CTAs/SM)
    cudaFuncSetAttribute(qkv_gemm, cudaFuncAttributeMaxDynamicSharedMemorySize, SMEM);
    cudaFuncSetAttribute(mgemm<6>, cudaFuncAttributeMaxDynamicSharedMemorySize, SMEM2);
    cudaFuncSetAttribute(mgemm<8>, cudaFuncAttributeMaxDynamicSharedMemorySize, SMEM2);
    cudaFuncSetAttribute(fa_kernel, cudaFuncAttributeMaxDynamicSharedMemorySize, FA_SMEM);

    const float qscale = 0.08838834764831843f;  // 1/sqrt(128)
    dim3 tt(32, 8);

    // weight transpose+split (vectorized)
    wsplitT4<<<dim3(H_/32, H_/64, 4), tt>>>(wq, wk, wv, wo,
        wqk_h, wqk_l, wqk_h + (size_t)H_*H_, wqk_l + (size_t)H_*H_,
        wvt_h, wvt_l, wot_h, wot_l);
    wsplitT<<<dim3(FF_/32, H_/64),  tt>>>(w1, w1t_h, w1t_l, H_,  FF_);
    wsplitT<<<dim3(H_/32,  FF_/64), tt>>>(w2, w2t_h, w2t_l, FF_, H_);

    // LN1
    ln_kernel<<<M_, 256>>>(x, ln1s, ln1b, h_h, h_l);

    // merged QKV (z = 0:q scaled, 1:k, 2:v transposed)
    dim3 gqkv(H_/128, M_/128, 3);
    qkv_gemm<<<gqkv, 256, SMEM>>>(h_h, h_l, wqk_h, wqk_l, wvt_h, wvt_l,
                                  qk_h, qk_l, vt_h, vt_l, qscale);

    // fused flash attention
    dim3 gfa(1, T_/128, NBATCH);
    fa_kernel<<<gfa, 256, FA_SMEM>>>(qk_h, qk_l,
                                     qk_h + (size_t)M_*H_, qk_l + (size_t)M_*H_,
                                     vt_h, vt_l, at_h, at_l);

    // Wo split-K=2 -> partials; fused combine + residual + LN2
    dim3 gwo(H_/128, M_/128, 2);
    mgemm<8><<<gwo, 256, SMEM2>>>(at_h, at_l, wot_h, wot_l, pp, nullptr, nullptr,
                                  nullptr, nullptr, H_/2, H_, H_, 1.0f,
                                  (size_t)(H_/2), (size_t)(H_/2));
    combine_ln<<<M_, 256>>>(pp, pp + (size_t)M_*H_, x, ln2s, ln2b, x2, h_h, h_l);

    // ffn = gelu(h @ w1 + b1)
    dim3 gf1(FF_/128, M_/128);
    mgemm<6><<<gf1, 256, SMEM2>>>(h_h, h_l, w1t_h, w1t_l, nullptr, f_h, f_l,
                                  b1, nullptr, H_, H_, H_, 1.0f, 0, 0);

    // FFN2 split-K=2 -> partials; combine adds x2 + b2 -> out
    dim3 gf2(H_/128, M_/128, 2);
    mgemm<8><<<gf2, 256, SMEM2>>>(f_h, f_l, w2t_h, w2t_l, pp, nullptr, nullptr,
                                  nullptr, nullptr, FF_/2, FF_, FF_, 1.0f,
                                  (size_t)(FF_/2), (size_t)(FF_/2));
    combine2<<<(M_*H_)/1024, 256>>>(pp, pp + (size_t)M_*H_, x2, b2, out);
}

// round 17
// speedup vs baseline: 1.0460x; 1.0460x over previous
#include <cuda_runtime.h>
#include <cuda_bf16.h>
#include <math.h>
#include <stdint.h>

// Problem constants
#define B_   2
#define T_   2048
#define H_   2048
#define NH_  16
#define HD_  128
#define FF_  8192
#define M_   (B_*T_)       // 4096
#define NBATCH (B_*NH_)    // 32
#define EPS_ 1e-5f

// ---------------- scratch (static device globals) ----------------
__device__ __align__(128) __nv_bfloat16 g_h_h [(size_t)M_*H_];
__device__ __align__(128) __nv_bfloat16 g_h_l [(size_t)M_*H_];
__device__ __align__(128) __nv_bfloat16 g_qk_h[(size_t)2*M_*H_];  // q then k, [B,NH,T,HD]
__device__ __align__(128) __nv_bfloat16 g_qk_l[(size_t)2*M_*H_];
__device__ __align__(128) __nv_bfloat16 g_vt_h[(size_t)M_*H_];    // [B,NH,HD,T]
__device__ __align__(128) __nv_bfloat16 g_vt_l[(size_t)M_*H_];
__device__ __align__(128) __nv_bfloat16 g_at_h[(size_t)M_*H_];    // attn [B,T,H]
__device__ __align__(128) __nv_bfloat16 g_at_l[(size_t)M_*H_];
__device__ __align__(128) __nv_bfloat16 g_f_h [(size_t)M_*FF_];
__device__ __align__(128) __nv_bfloat16 g_f_l [(size_t)M_*FF_];
__device__ __align__(128) float g_x2[(size_t)M_*H_];
__device__ __align__(128) float g_pp[(size_t)2*M_*H_];            // split-K partials
// transposed split weights [N,K]
__device__ __align__(128) __nv_bfloat16 g_wqk_h[(size_t)2*H_*H_]; // wq then wk
__device__ __align__(128) __nv_bfloat16 g_wqk_l[(size_t)2*H_*H_];
__device__ __align__(128) __nv_bfloat16 g_wv_h[(size_t)H_*H_];
__device__ __align__(128) __nv_bfloat16 g_wv_l[(size_t)H_*H_];
__device__ __align__(128) __nv_bfloat16 g_wo_h[(size_t)H_*H_];
__device__ __align__(128) __nv_bfloat16 g_wo_l[(size_t)H_*H_];
__device__ __align__(128) __nv_bfloat16 g_w1_h[(size_t)FF_*H_];
__device__ __align__(128) __nv_bfloat16 g_w1_l[(size_t)FF_*H_];
__device__ __align__(128) __nv_bfloat16 g_w2_h[(size_t)H_*FF_];
__device__ __align__(128) __nv_bfloat16 g_w2_l[(size_t)H_*FF_];

// ---------------- PTX helpers (all arch-portable: sm_80+) ----------------
__device__ __forceinline__ uint32_t smem_u32(const void* p) {
    uint32_t a;
    asm("{ .reg .u64 t; cvta.to.shared.u64 t, %1; cvt.u32.u64 %0, t; }" : "=r"(a) : "l"(p));
    return a;
}
#define SW128(o) ((o) ^ (((o) >> 3) & 0x70))

__device__ __forceinline__ void cpa16(uint32_t s, const void* g) {
    asm volatile("cp.async.cg.shared.global [%0], [%1], 16;" :: "r"(s), "l"(g) : "memory");
}
__device__ __forceinline__ void cpa_commit() {
    asm volatile("cp.async.commit_group;" ::: "memory");
}
template<int N> __device__ __forceinline__ void cpa_wait() {
    asm volatile("cp.async.wait_group %0;" :: "n"(N) : "memory");
}

#define LDSM4(r, addr) \
    asm volatile("ldmatrix.sync.aligned.m8n8.x4.shared.b16 {%0,%1,%2,%3}, [%4];" \
        : "=r"((r)[0]), "=r"((r)[1]), "=r"((r)[2]), "=r"((r)[3]) : "r"(addr))

#define MMA_BF16(d, a, b) \
    asm volatile("mma.sync.aligned.m16n8k16.row.col.f32.bf16.bf16.f32 " \
        "{%0,%1,%2,%3},{%4,%5,%6,%7},{%8,%9},{%0,%1,%2,%3};" \
        : "+f"((d)[0]), "+f"((d)[1]), "+f"((d)[2]), "+f"((d)[3]) \
        : "r"((a)[0]), "r"((a)[1]), "r"((a)[2]), "r"((a)[3]), "r"((b)[0]), "r"((b)[1]))

// ---------------- misc helpers ----------------
__device__ __forceinline__ float gelu_tanh_f(float x) {
    float x3 = x * x * x;
    float t  = tanhf(0.7978845608028654f * (x + 0.044715f * x3));
    return 0.5f * x * (1.0f + t);
}
__device__ __forceinline__ void st_split2(__nv_bfloat16* ph, __nv_bfloat16* pl, float a, float b) {
    __nv_bfloat16 ha = __float2bfloat16(a), hb = __float2bfloat16(b);
    __nv_bfloat162 hp = __halves2bfloat162(ha, hb);
    __nv_bfloat162 lp = __halves2bfloat162(__float2bfloat16(a - __bfloat162float(ha)),
                                           __float2bfloat16(b - __bfloat162float(hb)));
    *(uint32_t*)ph = *(uint32_t*)&hp;
    *(uint32_t*)pl = *(uint32_t*)&lp;
}
__device__ __forceinline__ uint32_t pack_split_hi(float a, float b, uint32_t* lo) {
    __nv_bfloat16 ha = __float2bfloat16(a), hb = __float2bfloat16(b);
    __nv_bfloat162 hp = __halves2bfloat162(ha, hb);
    __nv_bfloat162 lp = __halves2bfloat162(__float2bfloat16(a - __bfloat162float(ha)),
                                           __float2bfloat16(b - __bfloat162float(hb)));
    *lo = *(uint32_t*)&lp;
    return *(uint32_t*)&hp;
}

// ---------------- weight transpose + split (vectorized) ----------------
__global__ __launch_bounds__(256)
void wsplitT(const float* __restrict__ W, __nv_bfloat16* __restrict__ Th,
             __nv_bfloat16* __restrict__ Tl, int K, int N)
{
    __shared__ float t[64][33];
    int n0 = blockIdx.x * 32, k0 = blockIdx.y * 64;
    int tx = threadIdx.x, ty = threadIdx.y;
#pragma unroll
    for (int r = ty; r < 64; r += 8)
        t[r][tx] = W[(size_t)(k0 + r) * N + n0 + tx];
    __syncthreads();
#pragma unroll
    for (int n = ty; n < 32; n += 8) {
        float a = t[2 * tx][n], b = t[2 * tx + 1][n];
        uint32_t lo;
        uint32_t hi = pack_split_hi(a, b, &lo);
        size_t idx = (size_t)(n0 + n) * K + k0 + 2 * tx;
        *(uint32_t*)(Th + idx) = hi;
        *(uint32_t*)(Tl + idx) = lo;
    }
}

__global__ __launch_bounds__(256)
void wsplitT4(const float* __restrict__ w0, const float* __restrict__ w1,
              const float* __restrict__ w2, const float* __restrict__ w3,
              __nv_bfloat16* __restrict__ t0h, __nv_bfloat16* __restrict__ t0l,
              __nv_bfloat16* __restrict__ t1h, __nv_bfloat16* __restrict__ t1l,
              __nv_bfloat16* __restrict__ t2h, __nv_bfloat16* __restrict__ t2l,
              __nv_bfloat16* __restrict__ t3h, __nv_bfloat16* __restrict__ t3l)
{
    __shared__ float t[64][33];
    int z = blockIdx.z;
    const float* W = (z == 0) ? w0 : (z == 1) ? w1 : (z == 2) ? w2 : w3;
    __nv_bfloat16* Th = (z == 0) ? t0h : (z == 1) ? t1h : (z == 2) ? t2h : t3h;
    __nv_bfloat16* Tl = (z == 0) ? t0l : (z == 1) ? t1l : (z == 2) ? t2l : t3l;
    int n0 = blockIdx.x * 32, k0 = blockIdx.y * 64;
    int tx = threadIdx.x, ty = threadIdx.y;
#pragma unroll
    for (int r = ty; r < 64; r += 8)
        t[r][tx] = W[(size_t)(k0 + r) * H_ + n0 + tx];
    __syncthreads();
#pragma unroll
    for (int n = ty; n < 32; n += 8) {
        float a = t[2 * tx][n], b = t[2 * tx + 1][n];
        uint32_t lo;
        uint32_t hi = pack_split_hi(a, b, &lo);
        size_t idx = (size_t)(n0 + n) * H_ + k0 + 2 * tx;
        *(uint32_t*)(Th + idx) = hi;
        *(uint32_t*)(Tl + idx) = lo;
    }
}

// ---------------- LayerNorm -> bf16 hi/lo ----------------
__global__ __launch_bounds__(256)
void ln_kernel(const float* __restrict__ x, const float* __restrict__ sc,
               const float* __restrict__ sh,
               __nv_bfloat16* __restrict__ oh, __nv_bfloat16* __restrict__ ol)
{
    __shared__ float red[8];
    int row = blockIdx.x;
    int tid = threadIdx.x;
    const float* xr = x + (size_t)row * H_;

    float v[8];
    float s = 0.f;
#pragma unroll
    for (int i = 0; i < 8; i++) { v[i] = xr[i * 256 + tid]; s += v[i]; }
#pragma unroll
    for (int o = 16; o > 0; o >>= 1) s += __shfl_xor_sync(0xffffffffu, s, o);
    if ((tid & 31) == 0) red[tid >> 5] = s;
    __syncthreads();
    float tot = 0.f;
#pragma unroll
    for (int i = 0; i < 8; i++) tot += red[i];
    __syncthreads();
    float mean = tot * (1.0f / H_);

    float s2 = 0.f;
#pragma unroll
    for (int i = 0; i < 8; i++) { float d = v[i] - mean; s2 += d * d; }
#pragma unroll
    for (int o = 16; o > 0; o >>= 1) s2 += __shfl_xor_sync(0xffffffffu, s2, o);
    if ((tid & 31) == 0) red[tid >> 5] = s2;
    __syncthreads();
    float tot2 = 0.f;
#pragma unroll
    for (int i = 0; i < 8; i++) tot2 += red[i];

    float inv = rsqrtf(tot2 * (1.0f / H_) + EPS_);
    size_t rb = (size_t)row * H_;
#pragma unroll
    for (int i = 0; i < 8; i++) {
        int col = i * 256 + tid;
        float val = sc[col] * ((v[i] - mean) * inv) + sh[col];
        __nv_bfloat16 h = __float2bfloat16(val);
        oh[rb + col] = h;
        ol[rb + col] = __float2bfloat16(val - __bfloat162float(h));
    }
}

// ---------------- fused split-K combine (Wo) + residual + LN2 ----------------
__global__ __launch_bounds__(256)
void combine_ln(const float* __restrict__ p0, const float* __restrict__ p1,
                const float* __restrict__ res,
                const float* __restrict__ sc, const float* __restrict__ sh,
                float* __restrict__ x2, __nv_bfloat16* __restrict__ oh,
                __nv_bfloat16* __restrict__ ol)
{
    __shared__ float red[8];
    int row = blockIdx.x;
    int tid = threadIdx.x;
    size_t rb = (size_t)row * H_;

    float v[8];
    float s = 0.f;
#pragma unroll
    for (int i = 0; i < 8; i++) {
        int col = i * 256 + tid;
        float val = p0[rb + col] + p1[rb + col] + res[rb + col];
        x2[rb + col] = val;
        v[i] = val;
        s += val;
    }
#pragma unroll
    for (int o = 16; o > 0; o >>= 1) s += __shfl_xor_sync(0xffffffffu, s, o);
    if ((tid & 31) == 0) red[tid >> 5] = s;
    __syncthreads();
    float tot = 0.f;
#pragma unroll
    for (int i = 0; i < 8; i++) tot += red[i];
    __syncthreads();
    float mean = tot * (1.0f / H_);

    float s2 = 0.f;
#pragma unroll
    for (int i = 0; i < 8; i++) { float d = v[i] - mean; s2 += d * d; }
#pragma unroll
    for (int o = 16; o > 0; o >>= 1) s2 += __shfl_xor_sync(0xffffffffu, s2, o);
    if ((tid & 31) == 0) red[tid >> 5] = s2;
    __syncthreads();
    float tot2 = 0.f;
#pragma unroll
    for (int i = 0; i < 8; i++) tot2 += red[i];

    float inv = rsqrtf(tot2 * (1.0f / H_) + EPS_);
#pragma unroll
    for (int i = 0; i < 8; i++) {
        int col = i * 256 + tid;
        float val = sc[col] * ((v[i] - mean) * inv) + sh[col];
        __nv_bfloat16 h = __float2bfloat16(val);
        oh[rb + col] = h;
        ol[rb + col] = __float2bfloat16(val - __bfloat162float(h));
    }
}

// ---------------- split-K combine: out = p0 + p1 + res + bias ----------------
__global__ __launch_bounds__(256)
void combine2(const float* __restrict__ p0, const float* __restrict__ p1,
              const float* __restrict__ res, const float* __restrict__ bias,
              float* __restrict__ out)
{
    size_t i4 = (size_t)blockIdx.x * 256 + threadIdx.x;
    size_t base = i4 * 4;
    float4 a = *(const float4*)(p0 + base);
    float4 b = *(const float4*)(p1 + base);
    float4 r = *(const float4*)(res + base);
    float4 o;
    o.x = a.x + b.x + r.x;
    o.y = a.y + b.y + r.y;
    o.z = a.z + b.z + r.z;
    o.w = a.w + b.w + r.w;
    if (bias) {
        int col = (int)(base & (H_ - 1));
        o.x += bias[col]; o.y += bias[col + 1]; o.z += bias[col + 2]; o.w += bias[col + 3];
    }
    *(float4*)(out + base) = o;
}

// ---------------- merged QKV GEMM (z=0:q *alpha, 1:k, 2:v transposed) ----------------
__global__ __launch_bounds__(256)
void qkv_gemm(const __nv_bfloat16* __restrict__ Ah, const __nv_bfloat16* __restrict__ Al,
              const __nv_bfloat16* __restrict__ Bqkh, const __nv_bfloat16* __restrict__ Bqkl,
              const __nv_bfloat16* __restrict__ Bvh, const __nv_bfloat16* __restrict__ Bvl,
              __nv_bfloat16* __restrict__ Cqh, __nv_bfloat16* __restrict__ Cql,
              __nv_bfloat16* __restrict__ Cvh, __nv_bfloat16* __restrict__ Cvl,
              float alpha)
{
    int bn = blockIdx.x, bm = blockIdx.y, z = blockIdx.z;
    const int NCH = H_ >> 6;

    extern __shared__ char smem[];
    uint32_t sb = smem_u32(smem);
    const uint32_t STG = 65536;

    int tid = threadIdx.x, wid = tid >> 5, lane = tid & 31;
    int wm = wid >> 1, wn = wid & 1;

    const __nv_bfloat16* Agh = Ah + (size_t)(bm * 128) * H_;
    const __nv_bfloat16* Agl = Al + (size_t)(bm * 128) * H_;
    const __nv_bfloat16* Bgh = ((z == 2) ? Bvh : Bqkh + (size_t)z * H_ * H_) + (size_t)(bn * 128) * H_;
    const __nv_bfloat16* Bgl = ((z == 2) ? Bvl : Bqkl + (size_t)z * H_ * H_) + (size_t)(bn * 128) * H_;

    auto ldst = [&](int i, int st) {
        uint32_t base = sb + st * STG;
        int k0 = i << 6;
#pragma unroll
        for (int p = tid; p < 1024; p += 256) {
            int r = p >> 3, c = p & 7;
            uint32_t so = SW128(r * 128 + c * 16);
            size_t go = (size_t)r * H_ + k0 + c * 8;
            cpa16(base + so,         Agh + go);
            cpa16(base + 16384 + so, Agl + go);
            cpa16(base + 32768 + so, Bgh + go);
            cpa16(base + 49152 + so, Bgl + go);
        }
        cpa_commit();
    };

    float acc[2][8][4];
#pragma unroll
    for (int mi = 0; mi < 2; mi++)
#pragma unroll
        for (int ni = 0; ni < 8; ni++)
#pragma unroll
            for (int r = 0; r < 4; r++) acc[mi][ni][r] = 0.f;

    ldst(0, 0);

    for (int i = 0; i < NCH; i++) {
        int st = i & 1;
        cpa_wait<0>();
        __syncthreads();
        if (i + 1 < NCH) ldst(i + 1, (i + 1) & 1);

        uint32_t base = sb + st * STG;
#pragma unroll
        for (int ks = 0; ks < 4; ks++) {
            uint32_t ah[2][4], al[2][4];
#pragma unroll
            for (int mi = 0; mi < 2; mi++) {
                int row = wm * 32 + mi * 16 + (lane & 15);
                uint32_t kb = ks * 32 + ((lane >> 4) << 4);
                uint32_t ad = base + SW128((uint32_t)(row * 128) + kb);
                LDSM4(ah[mi], ad);
                LDSM4(al[mi], ad + 16384);
            }
#pragma unroll
            for (int g = 0; g < 4; g++) {
                int nrow = wn * 64 + g * 16 + (lane & 7) + ((lane >> 4) << 3);
                uint32_t kb = ks * 32 + (((lane >> 3) & 1) << 4);
                uint32_t ad = base + 32768 + SW128((uint32_t)(nrow * 128) + kb);
                uint32_t bh4[4], bl4[4];
                LDSM4(bh4, ad);
                LDSM4(bl4, ad + 16384);
#pragma unroll
                for (int sub = 0; sub < 2; sub++) {
                    int ni = g * 2 + sub;
#pragma unroll
                    for (int mi = 0; mi < 2; mi++) {
                        MMA_BF16(acc[mi][ni], ah[mi], &bh4[sub * 2]);
                        MMA_BF16(acc[mi][ni], ah[mi], &bl4[sub * 2]);
                        MMA_BF16(acc[mi][ni], al[mi], &bh4[sub * 2]);
                    }
                }
            }
        }
    }

    if (z == 2) {
        __syncthreads();
        float* sf = (float*)smem;                       // [128][132]
#pragma unroll
        for (int mi = 0; mi < 2; mi++)
#pragma unroll
            for (int ni = 0; ni < 8; ni++)
#pragma unroll
                for (int half = 0; half < 2; half++) {
                    int r = wm * 32 + mi * 16 + (lane >> 2) + half * 8;
                    int c = wn * 64 + ni * 8 + (lane & 3) * 2;
                    sf[r * 132 + c]     = acc[mi][ni][half * 2 + 0];
                    sf[r * 132 + c + 1] = acc[mi][ni][half * 2 + 1];
                }
        __syncthreads();

        int d  = tid >> 1;
        int t0 = (tid & 1) * 64;
        int b  = (bm * 128) >> 11;
        int hh = bn;
        int tloc = (bm & (T_ / 128 - 1)) * 128;
        size_t obase = ((size_t)(b * NH_ + hh) * HD_ + d) * T_ + (size_t)tloc + t0;

        uint32_t hbuf[32], lbuf[32];
#pragma unroll
        for (int q = 0; q < 32; q++) {
            float a  = sf[(t0 + 2 * q)     * 132 + d];
            float c2 = sf[(t0 + 2 * q + 1) * 132 + d];
            hbuf[q] = pack_split_hi(a, c2, &lbuf[q]);
        }
        uint4* ph4 = (uint4*)(Cvh + obase);
        uint4* pl4 = (uint4*)(Cvl + obase);
#pragma unroll
        for (int g = 0; g < 8; g++) {
            ph4[g] = make_uint4(hbuf[4*g], hbuf[4*g+1], hbuf[4*g+2], hbuf[4*g+3]);
            pl4[g] = make_uint4(lbuf[4*g], lbuf[4*g+1], lbuf[4*g+2], lbuf[4*g+3]);
        }
        return;
    }

    float a = (z == 0) ? alpha : 1.0f;
#pragma unroll
    for (int mi = 0; mi < 2; mi++) {
#pragma unroll
        for (int ni = 0; ni < 8; ni++) {
            int row0 = bm * 128 + wm * 32 + mi * 16 + (lane >> 2);
            int col  = bn * 128 + wn * 64 + ni * 8 + (lane & 3) * 2;
#pragma unroll
            for (int half = 0; half < 2; half++) {
                int gm = row0 + half * 8;
                float v0 = acc[mi][ni][half * 2 + 0] * a;
                float v1 = acc[mi][ni][half * 2 + 1] * a;
                int b = gm >> 11, t = gm & (T_ - 1);
                int hh = col >> 7, d = col & 127;
                size_t idx = (size_t)z * M_ * H_ +
                             (((size_t)(b * NH_ + hh) * T_ + t) << 7) + d;
                st_split2(Cqh + idx, Cql + idx, v0, v1);
            }
        }
    }
}

// ---------------- mma.sync split-bf16 GEMM (FFN + Wo), BK=64, 1 CTA/SM ----------------
// stage (64KB): Ah@0, Al@16K, Bh@32K, Bl@48K (SW128); 2 stages = 128KB
// EPI: 6 bias+gelu -> hi/lo; 8 split-K f32 partial (z = k-half)
template<int EPI>
__global__ __launch_bounds__(256)
void mgemm(const __nv_bfloat16* __restrict__ Ah, const __nv_bfloat16* __restrict__ Al,
           const __nv_bfloat16* __restrict__ Bh, const __nv_bfloat16* __restrict__ Bl,
           float* __restrict__ Cf, __nv_bfloat16* __restrict__ Ch, __nv_bfloat16* __restrict__ Cl,
           const float* __restrict__ bias, const float* __restrict__ res,
           int K, int lda, int ldb, float alpha, size_t sA, size_t sB)
{
    int bn = blockIdx.x, bm = blockIdx.y, z = blockIdx.z;
    const int NCH = K >> 6;

    extern __shared__ char smem[];
    uint32_t sb = smem_u32(smem);
    const uint32_t STG = 65536;

    int tid = threadIdx.x, wid = tid >> 5, lane = tid & 31;
    int wm = wid >> 1, wn = wid & 1;

    const __nv_bfloat16* Agh = Ah + (size_t)z * sA + (size_t)(bm * 128) * lda;
    const __nv_bfloat16* Agl = Al + (size_t)z * sA + (size_t)(bm * 128) * lda;
    const __nv_bfloat16* Bgh = Bh + (size_t)z * sB + (size_t)(bn * 128) * ldb;
    const __nv_bfloat16* Bgl = Bl + (size_t)z * sB + (size_t)(bn * 128) * ldb;

    auto ldst = [&](int i, int st) {
        uint32_t base = sb + st * STG;
        int k0 = i << 6;
#pragma unroll
        for (int p = tid; p < 1024; p += 256) {
            int r = p >> 3, c = p & 7;
            uint32_t so = SW128(r * 128 + c * 16);
            size_t goa = (size_t)r * lda + k0 + c * 8;
            size_t gob = (size_t)r * ldb + k0 + c * 8;
            cpa16(base + so,         Agh + goa);
            cpa16(base + 16384 + so, Agl + goa);
            cpa16(base + 32768 + so, Bgh + gob);
            cpa16(base + 49152 + so, Bgl + gob);
        }
        cpa_commit();
    };

    float acc[2][8][4];
#pragma unroll
    for (int mi = 0; mi < 2; mi++)
#pragma unroll
        for (int ni = 0; ni < 8; ni++)
#pragma unroll
            for (int r = 0; r < 4; r++) acc[mi][ni][r] = 0.f;

    ldst(0, 0);

    for (int i = 0; i < NCH; i++) {
        int st = i & 1;
        cpa_wait<0>();
        __syncthreads();
        if (i + 1 < NCH) ldst(i + 1, (i + 1) & 1);

        uint32_t base = sb + st * STG;
#pragma unroll
        for (int ks = 0; ks < 4; ks++) {
            uint32_t ah[2][4], al[2][4];
#pragma unroll
            for (int mi = 0; mi < 2; mi++) {
                int row = wm * 32 + mi * 16 + (lane & 15);
                uint32_t kb = ks * 32 + ((lane >> 4) << 4);
                uint32_t ad = base + SW128((uint32_t)(row * 128) + kb);
                LDSM4(ah[mi], ad);
                LDSM4(al[mi], ad + 16384);
            }
#pragma unroll
            for (int g = 0; g < 4; g++) {
                int nrow = wn * 64 + g * 16 + (lane & 7) + ((lane >> 4) << 3);
                uint32_t kb = ks * 32 + (((lane >> 3) & 1) << 4);
                uint32_t ad = base + 32768 + SW128((uint32_t)(nrow * 128) + kb);
                uint32_t bh4[4], bl4[4];
                LDSM4(bh4, ad);
                LDSM4(bl4, ad + 16384);
#pragma unroll
                for (int sub = 0; sub < 2; sub++) {
                    int ni = g * 2 + sub;
#pragma unroll
                    for (int mi = 0; mi < 2; mi++) {
                        MMA_BF16(acc[mi][ni], ah[mi], &bh4[sub * 2]);
                        MMA_BF16(acc[mi][ni], ah[mi], &bl4[sub * 2]);
                        MMA_BF16(acc[mi][ni], al[mi], &bh4[sub * 2]);
                    }
                }
            }
        }
    }

#pragma unroll
    for (int mi = 0; mi < 2; mi++) {
#pragma unroll
        for (int ni = 0; ni < 8; ni++) {
            int row0 = bm * 128 + wm * 32 + mi * 16 + (lane >> 2);
            int col  = bn * 128 + wn * 64 + ni * 8 + (lane & 3) * 2;
#pragma unroll
            for (int half = 0; half < 2; half++) {
                int gm = row0 + half * 8;
                float v0 = acc[mi][ni][half * 2 + 0];
                float v1 = acc[mi][ni][half * 2 + 1];

                if (EPI == 6) {
                    v0 = gelu_tanh_f(v0 + bias[col]);
                    v1 = gelu_tanh_f(v1 + bias[col + 1]);
                    size_t idx = (size_t)gm * FF_ + col;
                    st_split2(Ch + idx, Cl + idx, v0, v1);
                } else if (EPI == 8) {
                    float2* p = (float2*)(Cf + (size_t)z * M_ * H_ + (size_t)gm * H_ + col);
                    *p = make_float2(v0, v1);
                }
            }
        }
    }
}

// ---------------- fused flash attention ----------------
#define FA_SMEM 131072
__global__ __launch_bounds__(256)
void fa_kernel(const __nv_bfloat16* __restrict__ Qh, const __nv_bfloat16* __restrict__ Ql,
               const __nv_bfloat16* __restrict__ Kh, const __nv_bfloat16* __restrict__ Kl,
               const __nv_bfloat16* __restrict__ Vth, const __nv_bfloat16* __restrict__ Vtl,
               __nv_bfloat16* __restrict__ Ch, __nv_bfloat16* __restrict__ Cl)
{
    int bm = (int)gridDim.y - 1 - (int)blockIdx.y;   // longest first
    int z  = blockIdx.z;
    const int NCH = (bm + 1) * 2;                    // 64-token chunks

    extern __shared__ char smem[];
    uint32_t sb = smem_u32(smem);
    const uint32_t STG = 65536;

    int tid = threadIdx.x, w = tid >> 5, lane = tid & 31;

    const __nv_bfloat16* Qgh = Qh + (size_t)z * T_ * HD_ + (size_t)(bm * 128) * HD_;
    const __nv_bfloat16* Qgl = Ql + (size_t)z * T_ * HD_ + (size_t)(bm * 128) * HD_;
    const __nv_bfloat16* Kgh = Kh + (size_t)z * T_ * HD_;
    const __nv_bfloat16* Kgl = Kl + (size_t)z * T_ * HD_;
    const __nv_bfloat16* Vgh = Vth + (size_t)z * HD_ * T_;
    const __nv_bfloat16* Vgl = Vtl + (size_t)z * HD_ * T_;

#pragma unroll
    for (int p = tid; p < 2048; p += 256) {
        int r = p >> 4, c = p & 15;
        uint32_t so = (uint32_t)(c >> 3) * 16384 + SW128((uint32_t)(r * 128) + (c & 7) * 16);
        cpa16(sb + so,         Qgh + (size_t)r * HD_ + c * 8);
        cpa16(sb + 32768 + so, Qgl + (size_t)r * HD_ + c * 8);
    }
    cpa_commit();
    cpa_wait<0>();
    __syncthreads();

    uint32_t qh[8][4], ql[8][4];
#pragma unroll
    for (int ks = 0; ks < 8; ks++) {
        int row = w * 16 + (lane & 15);
        uint32_t kb = (uint32_t)(ks & 3) * 32 + ((lane >> 4) << 4);
        uint32_t ad = sb + (uint32_t)(ks >> 2) * 16384 + SW128((uint32_t)(row * 128) + kb);
        LDSM4(qh[ks], ad);
        LDSM4(ql[ks], ad + 32768);
    }
    __syncthreads();

    auto ldst = [&](int kt, int st) {
        uint32_t base = sb + st * STG;
#pragma unroll
        for (int p = tid; p < 1024; p += 256) {       // K: 64 rows x 256B
            int r = p >> 4, c = p & 15;
            uint32_t so = (uint32_t)(c >> 3) * 8192 + SW128((uint32_t)(r * 128) + (c & 7) * 16);
            size_t go = (size_t)(kt * 64 + r) * HD_ + c * 8;
            cpa16(base + so,         Kgh + go);
            cpa16(base + 16384 + so, Kgl + go);
        }
#pragma unroll
        for (int p = tid; p < 1024; p += 256) {       // V: 128 rows x 128B
            int r = p >> 3, c = p & 7;
            uint32_t so = SW128((uint32_t)(r * 128) + c * 16);
            size_t go = (size_t)r * T_ + kt * 64 + c * 8;
            cpa16(base + 32768 + so, Vgh + go);
            cpa16(base + 49152 + so, Vgl + go);
        }
        cpa_commit();
    };

    float m[2] = {-1e30f, -1e30f}, l[2] = {0.f, 0.f};
    float acc[16][4];
#pragma unroll
    for (int ni = 0; ni < 16; ni++)
#pragma unroll
        for (int r = 0; r < 4; r++) acc[ni][r] = 0.f;

    ldst(0, 0);

    int gmin = bm * 128 + w * 16;

    for (int i = 0; i < NCH; i++) {
        int st = i & 1;
        cpa_wait<0>();
        __syncthreads();
        if (i + 1 < NCH) ldst(i + 1, (i + 1) & 1);

        uint32_t base = sb + st * STG;

        float s[8][4];
#pragma unroll
        for (int ni = 0; ni < 8; ni++)
#pragma unroll
            for (int r = 0; r < 4; r++) s[ni][r] = 0.f;

#pragma unroll
        for (int ks = 0; ks < 8; ks++) {
            uint32_t kb = (uint32_t)(ks & 3) * 32 + (((lane >> 3) & 1) << 4);
            uint32_t kbase = base + (uint32_t)(ks >> 2) * 8192;
#pragma unroll
            for (int g = 0; g < 4; g++) {
                int nrow = g * 16 + (lane & 7) + ((lane >> 4) << 3);
                uint32_t ad = kbase + SW128((uint32_t)(nrow * 128) + kb);
                uint32_t kh4[4], kl4[4];
                LDSM4(kh4, ad);
                LDSM4(kl4, ad + 16384);
#pragma unroll
                for (int sub = 0; sub < 2; sub++) {
                    int ni = g * 2 + sub;
                    MMA_BF16(s[ni], qh[ks], &kh4[sub * 2]);
                    MMA_BF16(s[ni], qh[ks], &kl4[sub * 2]);
                    MMA_BF16(s[ni], ql[ks], &kh4[sub * 2]);
                }
            }
        }

        int jb = i * 64;
        if (jb + 63 > gmin) {
#pragma unroll
            for (int ni = 0; ni < 8; ni++)
#pragma unroll
                for (int half = 0; half < 2; half++) {
                    int gi2 = gmin + (lane >> 2) + half * 8;
                    int j0  = jb + ni * 8 + (lane & 3) * 2;
                    if (j0 > gi2)     s[ni][half * 2]     = -1e30f;
                    if (j0 + 1 > gi2) s[ni][half * 2 + 1] = -1e30f;
                }
        }

        uint32_t pah[4][4], pal[4][4];
        float rfac[2];
#pragma unroll
        for (int half = 0; half < 2; half++) {
            float mx = -1e30f;
#pragma unroll
            for (int ni = 0; ni < 8; ni++) {
                mx = fmaxf(mx, s[ni][half * 2]);
                mx = fmaxf(mx, s[ni][half * 2 + 1]);
            }
            mx = fmaxf(mx, __shfl_xor_sync(0xffffffffu, mx, 1));
            mx = fmaxf(mx, __shfl_xor_sync(0xffffffffu, mx, 2));
            float mnew = fmaxf(m[half], mx);
            rfac[half] = __expf(m[half] - mnew);
            m[half] = mnew;

            float psum = 0.f;
#pragma unroll
            for (int ni = 0; ni < 8; ni++) {
                float p0 = __expf(s[ni][half * 2]     - mnew);
                float p1 = __expf(s[ni][half * 2 + 1] - mnew);
                psum += p0 + p1;
                uint32_t lo;
                uint32_t hi = pack_split_hi(p0, p1, &lo);
                pah[ni >> 1][(ni & 1) * 2 + half] = hi;
                pal[ni >> 1][(ni & 1) * 2 + half] = lo;
            }
            psum += __shfl_xor_sync(0xffffffffu, psum, 1);
            psum += __shfl_xor_sync(0xffffffffu, psum, 2);
            l[half] = l[half] * rfac[half] + psum;
        }

#pragma unroll
        for (int ni = 0; ni < 16; ni++) {
            acc[ni][0] *= rfac[0]; acc[ni][1] *= rfac[0];
            acc[ni][2] *= rfac[1]; acc[ni][3] *= rfac[1];
        }

#pragma unroll
        for (int ks2 = 0; ks2 < 4; ks2++) {
            uint32_t kb = (uint32_t)ks2 * 32 + (((lane >> 3) & 1) << 4);
#pragma unroll
            for (int g = 0; g < 8; g++) {
                int nrow = g * 16 + (lane & 7) + ((lane >> 4) << 3);
                uint32_t ad = base + 32768 + SW128((uint32_t)(nrow * 128) + kb);
                uint32_t vh4[4], vl4[4];
                LDSM4(vh4, ad);
                LDSM4(vl4, ad + 16384);
#pragma unroll
                for (int sub = 0; sub < 2; sub++) {
                    int ni = g * 2 + sub;
                    MMA_BF16(acc[ni], pah[ks2], &vh4[sub * 2]);
                    MMA_BF16(acc[ni], pah[ks2], &vl4[sub * 2]);
                    MMA_BF16(acc[ni], pal[ks2], &vh4[sub * 2]);
                }
            }
        }
    }

    int b  = z >> 4, hh = z & 15;
#pragma unroll
    for (int half = 0; half < 2; half++) {
        float linv = 1.0f / l[half];
        int gm = gmin + (lane >> 2) + half * 8;
#pragma unroll
        for (int ni = 0; ni < 16; ni++) {
            int col = ni * 8 + (lane & 3) * 2;
            float v0 = acc[ni][half * 2]     * linv;
            float v1 = acc[ni][half * 2 + 1] * linv;
            size_t idx = ((size_t)(b * T_ + gm)) * H_ + hh * HD_ + col;
            st_split2(Ch + idx, Cl + idx, v0, v1);
        }
    }
}

// ---------------- launch ----------------
extern "C" void kernel_launch(void* const* d_in, const int* in_sizes, int n_in,
                              void* d_out, int out_size)
{
    (void)in_sizes; (void)n_in; (void)out_size;
    const float* x    = (const float*)d_in[0];
    const float* wq   = (const float*)d_in[1];
    const float* wk   = (const float*)d_in[2];
    const float* wv   = (const float*)d_in[3];
    const float* wo   = (const float*)d_in[4];
    const float* ln1s = (const float*)d_in[5];
    const float* ln1b = (const float*)d_in[6];
    const float* ln2s = (const float*)d_in[7];
    const float* ln2b = (const float*)d_in[8];
    const float* w1   = (const float*)d_in[9];
    const float* b1   = (const float*)d_in[10];
    const float* w2   = (const float*)d_in[11];
    const float* b2   = (const float*)d_in[12];
    float* out = (float*)d_out;

    __nv_bfloat16 *h_h,*h_l,*qk_h,*qk_l,*vt_h,*vt_l,*at_h,*at_l,*f_h,*f_l;
    __nv_bfloat16 *wqk_h,*wqk_l,*wvt_h,*wvt_l,*wot_h,*wot_l,*w1t_h,*w1t_l,*w2t_h,*w2t_l;
    float *x2, *pp;
    cudaGetSymbolAddress((void**)&h_h, g_h_h);   cudaGetSymbolAddress((void**)&h_l, g_h_l);
    cudaGetSymbolAddress((void**)&qk_h, g_qk_h); cudaGetSymbolAddress((void**)&qk_l, g_qk_l);
    cudaGetSymbolAddress((void**)&vt_h, g_vt_h); cudaGetSymbolAddress((void**)&vt_l, g_vt_l);
    cudaGetSymbolAddress((void**)&at_h, g_at_h); cudaGetSymbolAddress((void**)&at_l, g_at_l);
    cudaGetSymbolAddress((void**)&f_h, g_f_h);   cudaGetSymbolAddress((void**)&f_l, g_f_l);
    cudaGetSymbolAddress((void**)&wqk_h, g_wqk_h); cudaGetSymbolAddress((void**)&wqk_l, g_wqk_l);
    cudaGetSymbolAddress((void**)&wvt_h, g_wv_h); cudaGetSymbolAddress((void**)&wvt_l, g_wv_l);
    cudaGetSymbolAddress((void**)&wot_h, g_wo_h); cudaGetSymbolAddress((void**)&wot_l, g_wo_l);
    cudaGetSymbolAddress((void**)&w1t_h, g_w1_h); cudaGetSymbolAddress((void**)&w1t_l, g_w1_l);
    cudaGetSymbolAddress((void**)&w2t_h, g_w2_h); cudaGetSymbolAddress((void**)&w2t_l, g_w2_l);
    cudaGetSymbolAddress((void**)&x2, g_x2);
    cudaGetSymbolAddress((void**)&pp, g_pp);

    const int SMEM = 131072;   // 2 stages x 64KB
    cudaFuncSetAttribute(qkv_gemm, cudaFuncAttributeMaxDynamicSharedMemorySize, SMEM);
    cudaFuncSetAttribute(mgemm<6>, cudaFuncAttributeMaxDynamicSharedMemorySize, SMEM);
    cudaFuncSetAttribute(mgemm<8>, cudaFuncAttributeMaxDynamicSharedMemorySize, SMEM);
    cudaFuncSetAttribute(fa_kernel, cudaFuncAttributeMaxDynamicSharedMemorySize, FA_SMEM);

    const float qscale = 0.08838834764831843f;  // 1/sqrt(128)
    dim3 tt(32, 8);

    // weight transpose+split (vectorized)
    wsplitT4<<<dim3(H_/32, H_/64, 4), tt>>>(wq, wk, wv, wo,
        wqk_h, wqk_l, wqk_h + (size_t)H_*H_, wqk_l + (size_t)H_*H_,
        wvt_h, wvt_l, wot_h, wot_l);
    wsplitT<<<dim3(FF_/32, H_/64),  tt>>>(w1, w1t_h, w1t_l, H_,  FF_);
    wsplitT<<<dim3(H_/32,  FF_/64), tt>>>(w2, w2t_h, w2t_l, FF_, H_);

    // LN1
    ln_kernel<<<M_, 256>>>(x, ln1s, ln1b, h_h, h_l);

    // merged QKV (z = 0:q scaled, 1:k, 2:v transposed)
    dim3 gqkv(H_/128, M_/128, 3);
    qkv_gemm<<<gqkv, 256, SMEM>>>(h_h, h_l, wqk_h, wqk_l, wvt_h, wvt_l,
                                  qk_h, qk_l, vt_h, vt_l, qscale);

    // fused flash attention
    dim3 gfa(1, T_/128, NBATCH);
    fa_kernel<<<gfa, 256, FA_SMEM>>>(qk_h, qk_l,
                                     qk_h + (size_t)M_*H_, qk_l + (size_t)M_*H_,
                                     vt_h, vt_l, at_h, at_l);

    // Wo split-K=2 -> partials; fused combine + residual + LN2
    dim3 gwo(H_/128, M_/128, 2);
    mgemm<8><<<gwo, 256, SMEM>>>(at_h, at_l, wot_h, wot_l, pp, nullptr, nullptr,
                                 nullptr, nullptr, H_/2, H_, H_, 1.0f,
                                 (size_t)(H_/2), (size_t)(H_/2));
    combine_ln<<<M_, 256>>>(pp, pp + (size_t)M_*H_, x, ln2s, ln2b, x2, h_h, h_l);

    // ffn = gelu(h @ w1 + b1)
    dim3 gf1(FF_/128, M_/128);
    mgemm<6><<<gf1, 256, SMEM>>>(h_h, h_l, w1t_h, w1t_l, nullptr, f_h, f_l,
                                 b1, nullptr, H_, H_, H_, 1.0f, 0, 0);

    // FFN2 split-K=2 -> partials; combine adds x2 + b2 -> out
    dim3 gf2(H_/128, M_/128, 2);
    mgemm<8><<<gf2, 256, SMEM>>>(f_h, f_l, w2t_h, w2t_l, pp, nullptr, nullptr,
                                 nullptr, nullptr, FF_/2, FF_, FF_, 1.0f,
                                 (size_t)(FF_/2), (size_t)(FF_/2));
    combine2<<<(M_*H_)/1024, 256>>>(pp, pp + (size_t)M_*H_, x2, b2, out);
}